// round 3
// baseline (speedup 1.0000x reference)
#include <cuda_runtime.h>
#include <math.h>
#include <stdint.h>

// ---------------------------------------------------------------------------
// Problem constants
// ---------------------------------------------------------------------------
#define S_DIM   1024
#define B_DIM   4
#define D_DIM   1024
#define H_DIM   16
#define HD_DIM  64
#define DFF_DIM 4096
#define NTOK    4096          // S*B
#define BH      64            // B*H

// ---------------------------------------------------------------------------
// Device scratch (static __device__ globals — the sanctioned no-alloc path)
// ---------------------------------------------------------------------------
__device__ float g_wqin [3 * D_DIM * D_DIM];     // quantized in_proj  (3072x1024)
__device__ float g_wqout[D_DIM * D_DIM];         // quantized out_proj (1024x1024)
__device__ float g_w1q  [DFF_DIM * D_DIM];       // quantized w1       (4096x1024)
__device__ float g_w2q  [D_DIM * DFF_DIM];       // quantized w2       (1024x4096)

__device__ float g_src2 [NTOK * D_DIM];          // LN1 output
__device__ float g_qk   [NTOK * D_DIM];          // src2 + pos
__device__ float g_qko  [NTOK * 2 * D_DIM];      // q|k projection output [N,2048]
__device__ float g_vo   [NTOK * D_DIM];          // v projection output   [N,1024]
__device__ float g_q    [BH * S_DIM * HD_DIM];   // [b,h,s,d] (scaled)
__device__ float g_k    [BH * S_DIM * HD_DIM];   // [b,h,s,d]
__device__ float g_vT   [BH * HD_DIM * S_DIM];   // [b,h,d,s]  (transposed v)
__device__ float g_scores[(size_t)BH * S_DIM * S_DIM];   // 256 MB
__device__ float g_ctxh [BH * S_DIM * HD_DIM];   // [b,h,s,d]
__device__ float g_ctx  [NTOK * D_DIM];          // [s,b, h*64+d] row layout
__device__ float g_res1 [NTOK * D_DIM];          // src + attn_out
__device__ float g_src2b[NTOK * D_DIM];          // LN2 output
__device__ float g_hbuf [NTOK * DFF_DIM];        // FFN hidden (64 MB)

// ---------------------------------------------------------------------------
// LSQ weight quantization:  out = rint(clamp(w/a, -8, 7)) * a
// ---------------------------------------------------------------------------
__global__ void quant_kernel(const float* __restrict__ w, float* __restrict__ o,
                             int n, const float* __restrict__ alpha_p, float g)
{
    int i = blockIdx.x * blockDim.x + threadIdx.x;
    if (i >= n) return;
    float alpha = *alpha_p;
    float ag = alpha * g;
    float a  = ag + (alpha - ag);
    float q  = fminf(fmaxf(w[i] / a, -8.0f), 7.0f);
    o[i] = rintf(q) * a;
}

// ---------------------------------------------------------------------------
// LayerNorm over last dim (D=1024). One block per token row, 256 threads.
// Optionally also writes qk = ln_out + pos (for LN1).
// ---------------------------------------------------------------------------
__global__ void ln_kernel(const float* __restrict__ x,
                          const float* __restrict__ gamma,
                          const float* __restrict__ beta,
                          float* __restrict__ out,
                          const float* __restrict__ pos,   // nullable
                          float* __restrict__ qk)          // nullable
{
    const int n = blockIdx.x;
    const float* row = x + (size_t)n * D_DIM;
    __shared__ float sh[D_DIM];
    __shared__ float red[256];
    const int tid = threadIdx.x;

    float s = 0.0f;
    #pragma unroll
    for (int i = tid; i < D_DIM; i += 256) { float v = row[i]; sh[i] = v; s += v; }
    red[tid] = s;
    __syncthreads();
    for (int st = 128; st > 0; st >>= 1) {
        if (tid < st) red[tid] += red[tid + st];
        __syncthreads();
    }
    const float mean = red[0] * (1.0f / D_DIM);
    __syncthreads();

    float vs = 0.0f;
    #pragma unroll
    for (int i = tid; i < D_DIM; i += 256) { float d = sh[i] - mean; vs += d * d; }
    red[tid] = vs;
    __syncthreads();
    for (int st = 128; st > 0; st >>= 1) {
        if (tid < st) red[tid] += red[tid + st];
        __syncthreads();
    }
    const float var = red[0] * (1.0f / D_DIM);
    const float inv = rsqrtf(var + 1e-5f);

    #pragma unroll
    for (int i = tid; i < D_DIM; i += 256) {
        float y = (sh[i] - mean) * inv * gamma[i] + beta[i];
        out[(size_t)n * D_DIM + i] = y;
        if (qk) qk[(size_t)n * D_DIM + i] = y + pos[(size_t)n * D_DIM + i];
    }
}

// ---------------------------------------------------------------------------
// Big fp32 GEMM:  C[M,N] = A[M,K] * B[N,K]^T  (+bias, +res, relu)
// 128x128x8 tiles, 256 threads, 8x8 microtile, register-prefetch pipeline.
// Requires M%128==0, N%128==0, K%8==0.
// ---------------------------------------------------------------------------
#define TBM 128
#define TBN 128
#define TBK 8

__global__ void __launch_bounds__(256, 2)
gemm128(const float* __restrict__ A, const float* __restrict__ B,
        float* __restrict__ C, int M, int N, int K,
        const float* __restrict__ bias,
        const float* __restrict__ res,
        int relu)
{
    const int n0 = blockIdx.x * TBN;
    const int m0 = blockIdx.y * TBM;

    __shared__ float As[TBK][TBM];
    __shared__ float Bs[TBK][TBN];

    const int tid  = threadIdx.x;
    const int lrow = tid >> 1;            // 0..127
    const int lcol = (tid & 1) * 4;       // 0 or 4
    const int tx   = tid & 15;            // 0..15 : N direction
    const int ty   = tid >> 4;            // 0..15 : M direction

    float acc[8][8] = {};

    const float* Ap = A + (size_t)(m0 + lrow) * K + lcol;
    const float* Bp = B + (size_t)(n0 + lrow) * K + lcol;

    // prologue: fetch first k-tile into registers
    float4 av = *(const float4*)(Ap);
    float4 bv = *(const float4*)(Bp);

    for (int k0 = 0; k0 < K; k0 += TBK) {
        As[lcol + 0][lrow] = av.x; As[lcol + 1][lrow] = av.y;
        As[lcol + 2][lrow] = av.z; As[lcol + 3][lrow] = av.w;
        Bs[lcol + 0][lrow] = bv.x; Bs[lcol + 1][lrow] = bv.y;
        Bs[lcol + 2][lrow] = bv.z; Bs[lcol + 3][lrow] = bv.w;
        __syncthreads();

        // prefetch next k-tile (overlaps with FMA phase below)
        if (k0 + TBK < K) {
            av = *(const float4*)(Ap + k0 + TBK);
            bv = *(const float4*)(Bp + k0 + TBK);
        }

        #pragma unroll
        for (int kk = 0; kk < TBK; kk++) {
            float a[8], b[8];
            *(float4*)&a[0] = *(const float4*)&As[kk][ty * 8];
            *(float4*)&a[4] = *(const float4*)&As[kk][ty * 8 + 4];
            *(float4*)&b[0] = *(const float4*)&Bs[kk][tx * 8];
            *(float4*)&b[4] = *(const float4*)&Bs[kk][tx * 8 + 4];
            #pragma unroll
            for (int i = 0; i < 8; i++)
                #pragma unroll
                for (int j = 0; j < 8; j++)
                    acc[i][j] += a[i] * b[j];
        }
        __syncthreads();
    }

    #pragma unroll
    for (int i = 0; i < 8; i++) {
        const int m = m0 + ty * 8 + i;
        #pragma unroll
        for (int j = 0; j < 8; j++) {
            const int n = n0 + tx * 8 + j;
            float v = acc[i][j];
            if (bias) v += bias[n];
            if (res)  v += res[(size_t)m * N + n];
            if (relu) v = fmaxf(v, 0.0f);
            C[(size_t)m * N + n] = v;
        }
    }
}

// ---------------------------------------------------------------------------
// Generic batched fp32 GEMM (attention): C[M,N] = A[M,K] * B[N,K]^T
// 64x64x16 tiles, 256 threads, 4x4 microtile, register prefetch.
// ---------------------------------------------------------------------------
#define GBM 64
#define GBN 64
#define GBK 16

__global__ void gemm_abt(const float* __restrict__ Ab, const float* __restrict__ Bb,
                         float* __restrict__ Cb,
                         int M, int N, int K,
                         size_t sA, size_t sB, size_t sC)
{
    const float* A  = Ab + (size_t)blockIdx.z * sA;
    const float* Bm = Bb + (size_t)blockIdx.z * sB;
    float*       C  = Cb + (size_t)blockIdx.z * sC;

    const int n0 = blockIdx.x * GBN;
    const int m0 = blockIdx.y * GBM;

    __shared__ float As[GBK][GBM];
    __shared__ float Bs[GBK][GBN];

    const int tid = threadIdx.x;
    const int lr = tid >> 2;          // 0..63
    const int lk = (tid & 3) * 4;     // 0,4,8,12

    const int tr = tid >> 4;          // 0..15
    const int tc = tid & 15;          // 0..15

    float acc[4][4] = {};

    const float* Ap = A  + (size_t)(m0 + lr) * K + lk;
    const float* Bp = Bm + (size_t)(n0 + lr) * K + lk;

    float4 av = *(const float4*)(Ap);
    float4 bv = *(const float4*)(Bp);

    for (int k0 = 0; k0 < K; k0 += GBK) {
        As[lk + 0][lr] = av.x; As[lk + 1][lr] = av.y;
        As[lk + 2][lr] = av.z; As[lk + 3][lr] = av.w;
        Bs[lk + 0][lr] = bv.x; Bs[lk + 1][lr] = bv.y;
        Bs[lk + 2][lr] = bv.z; Bs[lk + 3][lr] = bv.w;
        __syncthreads();

        if (k0 + GBK < K) {
            av = *(const float4*)(Ap + k0 + GBK);
            bv = *(const float4*)(Bp + k0 + GBK);
        }

        #pragma unroll
        for (int kk = 0; kk < GBK; kk++) {
            float4 a = *(const float4*)&As[kk][tr * 4];
            float4 b = *(const float4*)&Bs[kk][tc * 4];
            acc[0][0] += a.x * b.x; acc[0][1] += a.x * b.y;
            acc[0][2] += a.x * b.z; acc[0][3] += a.x * b.w;
            acc[1][0] += a.y * b.x; acc[1][1] += a.y * b.y;
            acc[1][2] += a.y * b.z; acc[1][3] += a.y * b.w;
            acc[2][0] += a.z * b.x; acc[2][1] += a.z * b.y;
            acc[2][2] += a.z * b.z; acc[2][3] += a.z * b.w;
            acc[3][0] += a.w * b.x; acc[3][1] += a.w * b.y;
            acc[3][2] += a.w * b.z; acc[3][3] += a.w * b.w;
        }
        __syncthreads();
    }

    #pragma unroll
    for (int i = 0; i < 4; i++) {
        const int m = m0 + tr * 4 + i;
        #pragma unroll
        for (int j = 0; j < 4; j++) {
            const int n = n0 + tc * 4 + j;
            C[(size_t)m * N + n] = acc[i][j];
        }
    }
}

// ---------------------------------------------------------------------------
// Row softmax (length 1024), one block per row, single global read + write.
// ---------------------------------------------------------------------------
__global__ void softmax_kernel(float* __restrict__ p)
{
    float* row = p + (size_t)blockIdx.x * S_DIM;
    __shared__ float sh[S_DIM];
    __shared__ float red[256];
    const int tid = threadIdx.x;

    float m = -3.402823466e+38f;
    #pragma unroll
    for (int i = tid; i < S_DIM; i += 256) {
        float v = row[i];
        sh[i] = v;
        m = fmaxf(m, v);
    }
    red[tid] = m;
    __syncthreads();
    for (int st = 128; st > 0; st >>= 1) {
        if (tid < st) red[tid] = fmaxf(red[tid], red[tid + st]);
        __syncthreads();
    }
    m = red[0];
    __syncthreads();

    float s = 0.0f;
    #pragma unroll
    for (int i = tid; i < S_DIM; i += 256) {
        float e = expf(sh[i] - m);
        sh[i] = e;
        s += e;
    }
    red[tid] = s;
    __syncthreads();
    for (int st = 128; st > 0; st >>= 1) {
        if (tid < st) red[tid] += red[tid + st];
        __syncthreads();
    }
    const float inv = 1.0f / red[0];
    #pragma unroll
    for (int i = tid; i < S_DIM; i += 256) row[i] = sh[i] * inv;
}

// ---------------------------------------------------------------------------
// Reshape kernels
// ---------------------------------------------------------------------------
// qko [N, 2048] (row n = s*B+b)  ->  q[b,h,s,d]*0.125 , k[b,h,s,d]
__global__ void split_qk_kernel(const float* __restrict__ qko,
                                float* __restrict__ q, float* __restrict__ k)
{
    const int idx = blockIdx.x * 256 + threadIdx.x;   // over N*2048
    const int n = idx >> 11;
    const int c = idx & 2047;
    const int s = n >> 2, b = n & 3;
    const float v = qko[idx];
    if (c < 1024) {
        const int h = c >> 6, d = c & 63;
        q[(((size_t)(b * H_DIM + h) * S_DIM + s) << 6) + d] = v * 0.125f;
    } else {
        const int c2 = c - 1024;
        const int h = c2 >> 6, d = c2 & 63;
        k[(((size_t)(b * H_DIM + h) * S_DIM + s) << 6) + d] = v;
    }
}

// vo [N, 1024] -> vT[b,h,d,s]
__global__ void reshape_v_kernel(const float* __restrict__ vo, float* __restrict__ vT)
{
    const int idx = blockIdx.x * 256 + threadIdx.x;   // over N*1024
    const int n = idx >> 10;
    const int c = idx & 1023;
    const int s = n >> 2, b = n & 3;
    const int h = c >> 6, d = c & 63;
    vT[((size_t)(b * H_DIM + h) * HD_DIM + d) * S_DIM + s] = vo[idx];
}

// ctxh [bh, s, d] -> ctx[(s*B+b)*D + h*64+d]
__global__ void reshape_ctx_kernel(const float* __restrict__ ctxh, float* __restrict__ ctx)
{
    const int idx = blockIdx.x * 256 + threadIdx.x;   // over BH*S*HD
    const int bh  = idx >> 16;
    const int rem = idx & 65535;
    const int s = rem >> 6, d = rem & 63;
    const int b = bh >> 4, h = bh & 15;
    ctx[((size_t)(s * B_DIM + b) << 10) + h * HD_DIM + d] = ctxh[idx];
}

// ---------------------------------------------------------------------------
// Host side
// ---------------------------------------------------------------------------
static float* sym_addr(const void* symbol)
{
    void* p = 0;
    cudaGetSymbolAddress(&p, symbol);
    return (float*)p;
}

extern "C" void kernel_launch(void* const* d_in, const int* in_sizes, int n_in,
                              void* d_out, int out_size)
{
    (void)n_in; (void)out_size; (void)in_sizes;

    const float* src       = (const float*)d_in[0];
    const float* pos       = (const float*)d_in[1];
    const float* in_proj_w = (const float*)d_in[2];
    const float* alpha_in  = (const float*)d_in[3];
    const float* out_proj_w= (const float*)d_in[4];
    const float* alpha_out = (const float*)d_in[5];
    const float* w1        = (const float*)d_in[6];
    const float* b1        = (const float*)d_in[7];
    const float* alpha1    = (const float*)d_in[8];
    const float* w2        = (const float*)d_in[9];
    const float* b2        = (const float*)d_in[10];
    const float* alpha2    = (const float*)d_in[11];
    const float* ln1_g     = (const float*)d_in[12];
    const float* ln1_b     = (const float*)d_in[13];
    const float* ln2_g     = (const float*)d_in[14];
    const float* ln2_b     = (const float*)d_in[15];
    float* out = (float*)d_out;

    float* p_wqin  = sym_addr(g_wqin);
    float* p_wqout = sym_addr(g_wqout);
    float* p_w1q   = sym_addr(g_w1q);
    float* p_w2q   = sym_addr(g_w2q);
    float* p_src2  = sym_addr(g_src2);
    float* p_qk    = sym_addr(g_qk);
    float* p_qko   = sym_addr(g_qko);
    float* p_vo    = sym_addr(g_vo);
    float* p_q     = sym_addr(g_q);
    float* p_k     = sym_addr(g_k);
    float* p_vT    = sym_addr(g_vT);
    float* p_sc    = sym_addr(g_scores);
    float* p_ctxh  = sym_addr(g_ctxh);
    float* p_ctx   = sym_addr(g_ctx);
    float* p_res1  = sym_addr(g_res1);
    float* p_src2b = sym_addr(g_src2b);
    float* p_h     = sym_addr(g_hbuf);

    // ---- 1. quantize weights (QP = 7) -----------------------------------
    {
        const int n_in_proj = 3 * D_DIM * D_DIM;
        const int n_out     = D_DIM * D_DIM;
        const int n_w1      = DFF_DIM * D_DIM;
        const int n_w2      = D_DIM * DFF_DIM;
        const float gi = (float)(1.0 / sqrt((double)n_in_proj * 7.0));
        const float go = (float)(1.0 / sqrt((double)n_out * 7.0));
        const float g1 = (float)(1.0 / sqrt((double)n_w1 * 7.0));
        const float g2 = (float)(1.0 / sqrt((double)n_w2 * 7.0));
        quant_kernel<<<(n_in_proj + 255) / 256, 256>>>(in_proj_w, p_wqin, n_in_proj, alpha_in, gi);
        quant_kernel<<<(n_out     + 255) / 256, 256>>>(out_proj_w, p_wqout, n_out, alpha_out, go);
        quant_kernel<<<(n_w1      + 255) / 256, 256>>>(w1, p_w1q, n_w1, alpha1, g1);
        quant_kernel<<<(n_w2      + 255) / 256, 256>>>(w2, p_w2q, n_w2, alpha2, g2);
    }

    // ---- 2. LN1 (+ qk = src2 + pos) -------------------------------------
    ln_kernel<<<NTOK, 256>>>(src, ln1_g, ln1_b, p_src2, pos, p_qk);

    // ---- 3. projections (128x128 tile GEMM) ------------------------------
    // q|k : [4096,1024] @ [2048,1024]^T
    gemm128<<<dim3(2048 / TBN, NTOK / TBM), 256>>>(
        p_qk, p_wqin, p_qko, NTOK, 2048, D_DIM, 0, 0, 0);
    // v   : [4096,1024] @ [1024,1024]^T   (A = src2, B = rows 2048..3071)
    gemm128<<<dim3(1024 / TBN, NTOK / TBM), 256>>>(
        p_src2, p_wqin + (size_t)2048 * D_DIM, p_vo, NTOK, 1024, D_DIM, 0, 0, 0);

    // ---- 4. reshapes -----------------------------------------------------
    split_qk_kernel <<<(NTOK * 2048) / 256, 256>>>(p_qko, p_q, p_k);
    reshape_v_kernel<<<(NTOK * 1024) / 256, 256>>>(p_vo, p_vT);

    // ---- 5. scores = q @ k^T  (batched over 64 heads) --------------------
    gemm_abt<<<dim3(S_DIM / GBN, S_DIM / GBM, BH), 256>>>(
        p_q, p_k, p_sc, S_DIM, S_DIM, HD_DIM,
        (size_t)S_DIM * HD_DIM, (size_t)S_DIM * HD_DIM, (size_t)S_DIM * S_DIM);

    // ---- 6. softmax ------------------------------------------------------
    softmax_kernel<<<BH * S_DIM, 256>>>(p_sc);

    // ---- 7. ctx = attn @ v  (batched; B = vT so it is A·B^T form) --------
    gemm_abt<<<dim3(HD_DIM / GBN, S_DIM / GBM, BH), 256>>>(
        p_sc, p_vT, p_ctxh, S_DIM, HD_DIM, S_DIM,
        (size_t)S_DIM * S_DIM, (size_t)HD_DIM * S_DIM, (size_t)S_DIM * HD_DIM);

    // ---- 8. ctx reshape to [s,b,D] rows ---------------------------------
    reshape_ctx_kernel<<<(BH * S_DIM * HD_DIM) / 256, 256>>>(p_ctxh, p_ctx);

    // ---- 9. out_proj + residual(src) ------------------------------------
    gemm128<<<dim3(1024 / TBN, NTOK / TBM), 256>>>(
        p_ctx, p_wqout, p_res1, NTOK, D_DIM, D_DIM, 0, src, 0);

    // ---- 10. LN2 ---------------------------------------------------------
    ln_kernel<<<NTOK, 256>>>(p_res1, ln2_g, ln2_b, p_src2b, 0, 0);

    // ---- 11. FFN1: relu(src2b @ w1^T + b1) ------------------------------
    gemm128<<<dim3(DFF_DIM / TBN, NTOK / TBM), 256>>>(
        p_src2b, p_w1q, p_h, NTOK, DFF_DIM, D_DIM, b1, 0, 1);

    // ---- 12. FFN2: res1 + h @ w2^T + b2  -> output ----------------------
    gemm128<<<dim3(1024 / TBN, NTOK / TBM), 256>>>(
        p_h, p_w2q, out, NTOK, D_DIM, DFF_DIM, b2, p_res1, 0);
}

// round 7
// speedup vs baseline: 1.6584x; 1.6584x over previous
#include <cuda_runtime.h>
#include <cuda_bf16.h>
#include <mma.h>
#include <math.h>
#include <stdint.h>

using namespace nvcuda;

// ---------------------------------------------------------------------------
// Problem constants
// ---------------------------------------------------------------------------
#define S_DIM   1024
#define B_DIM   4
#define D_DIM   1024
#define H_DIM   16
#define HD_DIM  64
#define DFF_DIM 4096
#define NTOK    4096          // S*B
#define BH      64            // B*H

// ---------------------------------------------------------------------------
// Device scratch
// ---------------------------------------------------------------------------
__device__ __nv_bfloat16 g_wqin_b [3 * D_DIM * D_DIM];   // integer-valued Q (in_proj)
__device__ __nv_bfloat16 g_wqout_b[D_DIM * D_DIM];
__device__ __nv_bfloat16 g_w1q_b  [DFF_DIM * D_DIM];
__device__ __nv_bfloat16 g_w2q_b  [D_DIM * DFF_DIM];

// activation split pairs
__device__ __nv_bfloat16 g_ah[NTOK * DFF_DIM];           // pair A hi (32 MB)
__device__ __nv_bfloat16 g_al[NTOK * DFF_DIM];           // pair A lo
__device__ __nv_bfloat16 g_bh[NTOK * D_DIM];             // pair B hi (8 MB)
__device__ __nv_bfloat16 g_bl[NTOK * D_DIM];             // pair B lo

__device__ float g_qko  [NTOK * 2 * D_DIM];      // q|k projection output [N,2048]
__device__ float g_vo   [NTOK * D_DIM];          // v projection output   [N,1024]
__device__ float g_q    [BH * S_DIM * HD_DIM];   // [b,h,s,d] (scaled)
__device__ float g_k    [BH * S_DIM * HD_DIM];   // [b,h,s,d]
__device__ float g_vT   [BH * HD_DIM * S_DIM];   // [b,h,d,s]
__device__ float g_scores[(size_t)BH * S_DIM * S_DIM];   // 256 MB
__device__ float g_ctxh [BH * S_DIM * HD_DIM];   // [b,h,s,d]
__device__ float g_res1 [NTOK * D_DIM];          // src + attn_out

// ---------------------------------------------------------------------------
// LSQ quantization to INTEGER bf16:  o = bf16(rint(clamp(w/a,-8,7)))
// vectorized: 4 elems/thread.
// ---------------------------------------------------------------------------
__global__ void quantq_kernel(const float* __restrict__ w, __nv_bfloat16* __restrict__ o,
                              int n4, const float* __restrict__ alpha_p, float g)
{
    int i = blockIdx.x * blockDim.x + threadIdx.x;
    if (i >= n4) return;
    float alpha = *alpha_p;
    float ag = alpha * g;
    float a  = ag + (alpha - ag);
    float inv_a = 1.0f / a;
    float4 v = ((const float4*)w)[i];
    float q0 = rintf(fminf(fmaxf(v.x * inv_a, -8.0f), 7.0f));
    float q1 = rintf(fminf(fmaxf(v.y * inv_a, -8.0f), 7.0f));
    float q2 = rintf(fminf(fmaxf(v.z * inv_a, -8.0f), 7.0f));
    float q3 = rintf(fminf(fmaxf(v.w * inv_a, -8.0f), 7.0f));
    __nv_bfloat162* o2 = (__nv_bfloat162*)o;
    o2[i * 2 + 0] = __nv_bfloat162(__float2bfloat16(q0), __float2bfloat16(q1));
    o2[i * 2 + 1] = __nv_bfloat162(__float2bfloat16(q2), __float2bfloat16(q3));
}

// ---------------------------------------------------------------------------
// LayerNorm over last dim (D=1024), fused bf16 hi/lo split outputs.
//   y = (x-mean)*rsqrt(var+eps)*gamma + beta
//   (out_hi,out_lo)  = split(y)        [nullable]
//   (qk_hi,qk_lo)    = split(y + pos)  [nullable; pos required when set]
// ---------------------------------------------------------------------------
__global__ void ln_split_kernel(const float* __restrict__ x,
                                const float* __restrict__ gamma,
                                const float* __restrict__ beta,
                                const float* __restrict__ pos,        // nullable
                                __nv_bfloat16* __restrict__ out_hi,
                                __nv_bfloat16* __restrict__ out_lo,
                                __nv_bfloat16* __restrict__ qk_hi,
                                __nv_bfloat16* __restrict__ qk_lo)
{
    const int n = blockIdx.x;
    const float* row = x + (size_t)n * D_DIM;
    __shared__ float sh[D_DIM];
    __shared__ float red[256];
    const int tid = threadIdx.x;

    float s = 0.0f;
    #pragma unroll
    for (int i = tid; i < D_DIM; i += 256) { float v = row[i]; sh[i] = v; s += v; }
    red[tid] = s;
    __syncthreads();
    for (int st = 128; st > 0; st >>= 1) {
        if (tid < st) red[tid] += red[tid + st];
        __syncthreads();
    }
    const float mean = red[0] * (1.0f / D_DIM);
    __syncthreads();

    float vs = 0.0f;
    #pragma unroll
    for (int i = tid; i < D_DIM; i += 256) { float d = sh[i] - mean; vs += d * d; }
    red[tid] = vs;
    __syncthreads();
    for (int st = 128; st > 0; st >>= 1) {
        if (tid < st) red[tid] += red[tid + st];
        __syncthreads();
    }
    const float var = red[0] * (1.0f / D_DIM);
    const float inv = rsqrtf(var + 1e-5f);

    #pragma unroll
    for (int i = tid; i < D_DIM; i += 256) {
        const size_t off = (size_t)n * D_DIM + i;
        float y = (sh[i] - mean) * inv * gamma[i] + beta[i];
        if (out_hi) {
            __nv_bfloat16 h = __float2bfloat16(y);
            out_hi[off] = h;
            out_lo[off] = __float2bfloat16(y - __bfloat162float(h));
        }
        if (qk_hi) {
            float z = y + pos[off];
            __nv_bfloat16 h = __float2bfloat16(z);
            qk_hi[off] = h;
            qk_lo[off] = __float2bfloat16(z - __bfloat162float(h));
        }
    }
}

// ---------------------------------------------------------------------------
// bf16 tensor-core GEMM with hi/lo split activations and integer weights:
//   acc = (Ah+Al)[M,K] @ Q[N,K]^T ;  v = acc*a (+bias) (+res) (relu)
//   if Chi: (Chi,Clo) = split(v)   else  C = v
// 128x128 block tile, K-tile 32, 8 warps, warp tile 32x64 (WMMA 16x16x16).
// Requires M%128==0, N%128==0, K%32==0.
// ---------------------------------------------------------------------------
#define WTS 40   // smem row stride in bf16 elems (32 + 8 pad)

__global__ void __launch_bounds__(256, 1)
gemm_bf16(const __nv_bfloat16* __restrict__ Ah,
          const __nv_bfloat16* __restrict__ Al,
          const __nv_bfloat16* __restrict__ Bq,
          float* __restrict__ C,
          __nv_bfloat16* __restrict__ Chi,
          __nv_bfloat16* __restrict__ Clo,
          int M, int N, int K,
          const float* __restrict__ alpha_p, float gscale,
          const float* __restrict__ bias,
          const float* __restrict__ res,
          int relu)
{
    __shared__ __nv_bfloat16 Ahs[128 * WTS];
    __shared__ __nv_bfloat16 Als[128 * WTS];
    __shared__ __nv_bfloat16 Bs [128 * WTS];
    __shared__ float scratch[8 * 256];

    const int tid = threadIdx.x;
    const int n0 = blockIdx.x * 128;
    const int m0 = blockIdx.y * 128;

    const int w  = tid >> 5;
    const int wm = w & 3;             // 0..3 : M warp (32 rows each)
    const int wn = w >> 2;            // 0..1 : N warp (64 cols each)

    wmma::fragment<wmma::accumulator, 16, 16, 16, float> acc[2][4];
    #pragma unroll
    for (int i = 0; i < 2; i++)
        #pragma unroll
        for (int j = 0; j < 4; j++)
            wmma::fill_fragment(acc[i][j], 0.0f);

    uint2 pa[4], pl[4], pb[4];

    #define LOAD_TILE_REGS(k0)                                                  \
        _Pragma("unroll")                                                       \
        for (int p = 0; p < 4; p++) {                                           \
            int lin = tid + p * 256;                                            \
            int r = lin >> 3;                                                   \
            int c = (lin & 7) * 4;                                              \
            pa[p] = *(const uint2*)(Ah + (size_t)(m0 + r) * K + (k0) + c);      \
            pl[p] = *(const uint2*)(Al + (size_t)(m0 + r) * K + (k0) + c);      \
            pb[p] = *(const uint2*)(Bq + (size_t)(n0 + r) * K + (k0) + c);      \
        }

    LOAD_TILE_REGS(0)

    for (int k0 = 0; k0 < K; k0 += 32) {
        #pragma unroll
        for (int p = 0; p < 4; p++) {
            int lin = tid + p * 256;
            int r = lin >> 3;
            int c = (lin & 7) * 4;
            *(uint2*)&Ahs[r * WTS + c] = pa[p];
            *(uint2*)&Als[r * WTS + c] = pl[p];
            *(uint2*)&Bs [r * WTS + c] = pb[p];
        }
        __syncthreads();

        if (k0 + 32 < K) { LOAD_TILE_REGS(k0 + 32) }

        #pragma unroll
        for (int kk = 0; kk < 32; kk += 16) {
            wmma::fragment<wmma::matrix_a, 16, 16, 16, __nv_bfloat16, wmma::row_major> fh[2], fl[2];
            wmma::fragment<wmma::matrix_b, 16, 16, 16, __nv_bfloat16, wmma::col_major> fb[4];
            #pragma unroll
            for (int i = 0; i < 2; i++) {
                wmma::load_matrix_sync(fh[i], &Ahs[(wm * 32 + i * 16) * WTS + kk], WTS);
                wmma::load_matrix_sync(fl[i], &Als[(wm * 32 + i * 16) * WTS + kk], WTS);
            }
            #pragma unroll
            for (int j = 0; j < 4; j++)
                wmma::load_matrix_sync(fb[j], &Bs[(wn * 64 + j * 16) * WTS + kk], WTS);

            #pragma unroll
            for (int i = 0; i < 2; i++)
                #pragma unroll
                for (int j = 0; j < 4; j++) {
                    wmma::mma_sync(acc[i][j], fh[i], fb[j], acc[i][j]);
                    wmma::mma_sync(acc[i][j], fl[i], fb[j], acc[i][j]);
                }
        }
        __syncthreads();
    }

    // epilogue
    const float alpha = *alpha_p;
    const float ag = alpha * gscale;
    const float a  = ag + (alpha - ag);

    float* sw = &scratch[w * 256];
    const int lane = tid & 31;

    #pragma unroll
    for (int i = 0; i < 2; i++) {
        #pragma unroll
        for (int j = 0; j < 4; j++) {
            wmma::store_matrix_sync(sw, acc[i][j], 16, wmma::mem_row_major);
            __syncwarp();
            #pragma unroll
            for (int t = 0; t < 8; t++) {
                int idx = lane + t * 32;
                int r = idx >> 4, c = idx & 15;
                int m = m0 + wm * 32 + i * 16 + r;
                int n = n0 + wn * 64 + j * 16 + c;
                float v = sw[idx] * a;
                if (bias) v += bias[n];
                if (res)  v += res[(size_t)m * N + n];
                if (relu) v = fmaxf(v, 0.0f);
                const size_t off = (size_t)m * N + n;
                if (Chi) {
                    __nv_bfloat16 h = __float2bfloat16(v);
                    Chi[off] = h;
                    Clo[off] = __float2bfloat16(v - __bfloat162float(h));
                } else {
                    C[off] = v;
                }
            }
            __syncwarp();
        }
    }
}

// ---------------------------------------------------------------------------
// Batched fp32 GEMM (attention): C[M,N] = A[M,K] * B[N,K]^T
// 64x64x16 tiles, 256 threads, 4x4 microtile, register prefetch.
// ---------------------------------------------------------------------------
#define GBM 64
#define GBN 64
#define GBK 16

__global__ void gemm_abt(const float* __restrict__ Ab, const float* __restrict__ Bb,
                         float* __restrict__ Cb,
                         int M, int N, int K,
                         size_t sA, size_t sB, size_t sC)
{
    const float* A  = Ab + (size_t)blockIdx.z * sA;
    const float* Bm = Bb + (size_t)blockIdx.z * sB;
    float*       C  = Cb + (size_t)blockIdx.z * sC;

    const int n0 = blockIdx.x * GBN;
    const int m0 = blockIdx.y * GBM;

    __shared__ float As[GBK][GBM];
    __shared__ float Bs[GBK][GBN];

    const int tid = threadIdx.x;
    const int lr = tid >> 2;
    const int lk = (tid & 3) * 4;
    const int tr = tid >> 4;
    const int tc = tid & 15;

    float acc[4][4] = {};

    const float* Ap = A  + (size_t)(m0 + lr) * K + lk;
    const float* Bp = Bm + (size_t)(n0 + lr) * K + lk;

    float4 av = *(const float4*)(Ap);
    float4 bv = *(const float4*)(Bp);

    for (int k0 = 0; k0 < K; k0 += GBK) {
        As[lk + 0][lr] = av.x; As[lk + 1][lr] = av.y;
        As[lk + 2][lr] = av.z; As[lk + 3][lr] = av.w;
        Bs[lk + 0][lr] = bv.x; Bs[lk + 1][lr] = bv.y;
        Bs[lk + 2][lr] = bv.z; Bs[lk + 3][lr] = bv.w;
        __syncthreads();

        if (k0 + GBK < K) {
            av = *(const float4*)(Ap + k0 + GBK);
            bv = *(const float4*)(Bp + k0 + GBK);
        }

        #pragma unroll
        for (int kk = 0; kk < GBK; kk++) {
            float4 a = *(const float4*)&As[kk][tr * 4];
            float4 b = *(const float4*)&Bs[kk][tc * 4];
            acc[0][0] += a.x * b.x; acc[0][1] += a.x * b.y;
            acc[0][2] += a.x * b.z; acc[0][3] += a.x * b.w;
            acc[1][0] += a.y * b.x; acc[1][1] += a.y * b.y;
            acc[1][2] += a.y * b.z; acc[1][3] += a.y * b.w;
            acc[2][0] += a.z * b.x; acc[2][1] += a.z * b.y;
            acc[2][2] += a.z * b.z; acc[2][3] += a.z * b.w;
            acc[3][0] += a.w * b.x; acc[3][1] += a.w * b.y;
            acc[3][2] += a.w * b.z; acc[3][3] += a.w * b.w;
        }
        __syncthreads();
    }

    #pragma unroll
    for (int i = 0; i < 4; i++) {
        const int m = m0 + tr * 4 + i;
        #pragma unroll
        for (int j = 0; j < 4; j++) {
            const int n = n0 + tc * 4 + j;
            C[(size_t)m * N + n] = acc[i][j];
        }
    }
}

// ---------------------------------------------------------------------------
// Row softmax (length 1024), one block per row, single global read + write.
// ---------------------------------------------------------------------------
__global__ void softmax_kernel(float* __restrict__ p)
{
    float* row = p + (size_t)blockIdx.x * S_DIM;
    __shared__ float sh[S_DIM];
    __shared__ float red[256];
    const int tid = threadIdx.x;

    float m = -3.402823466e+38f;
    #pragma unroll
    for (int i = tid; i < S_DIM; i += 256) {
        float v = row[i];
        sh[i] = v;
        m = fmaxf(m, v);
    }
    red[tid] = m;
    __syncthreads();
    for (int st = 128; st > 0; st >>= 1) {
        if (tid < st) red[tid] = fmaxf(red[tid], red[tid + st]);
        __syncthreads();
    }
    m = red[0];
    __syncthreads();

    float s = 0.0f;
    #pragma unroll
    for (int i = tid; i < S_DIM; i += 256) {
        float e = expf(sh[i] - m);
        sh[i] = e;
        s += e;
    }
    red[tid] = s;
    __syncthreads();
    for (int st = 128; st > 0; st >>= 1) {
        if (tid < st) red[tid] += red[tid + st];
        __syncthreads();
    }
    const float inv = 1.0f / red[0];
    #pragma unroll
    for (int i = tid; i < S_DIM; i += 256) row[i] = sh[i] * inv;
}

// ---------------------------------------------------------------------------
// Reshape kernels (vectorized)
// ---------------------------------------------------------------------------
// qko [N, 2048] -> q[b,h,s,d]*0.125 , k[b,h,s,d].  4 elems/thread; the 4
// consecutive c values share h (c%4==0 start) so the destination is one
// contiguous 4-aligned float4 run.
__global__ void split_qk_kernel(const float* __restrict__ qko,
                                float* __restrict__ q, float* __restrict__ k)
{
    const int i4 = blockIdx.x * 256 + threadIdx.x;    // over N*2048/4
    const int idx = i4 * 4;
    const int n = idx >> 11;
    const int c = idx & 2047;
    const int s = n >> 2, b = n & 3;
    float4 v = ((const float4*)qko)[i4];
    if (c < 1024) {
        const int h = c >> 6, d = c & 63;
        float4 o = make_float4(v.x * 0.125f, v.y * 0.125f, v.z * 0.125f, v.w * 0.125f);
        *(float4*)&q[(((size_t)(b * H_DIM + h) * S_DIM + s) << 6) + d] = o;
    } else {
        const int c2 = c - 1024;
        const int h = c2 >> 6, d = c2 & 63;
        *(float4*)&k[(((size_t)(b * H_DIM + h) * S_DIM + s) << 6) + d] = v;
    }
}

// vo [N, 1024] -> vT[b,h,d,s]  (vec4 read, scattered scalar writes)
__global__ void reshape_v_kernel(const float* __restrict__ vo, float* __restrict__ vT)
{
    const int i4 = blockIdx.x * 256 + threadIdx.x;    // over N*1024/4
    const int idx = i4 * 4;
    const int n = idx >> 10;
    const int c = idx & 1023;
    const int s = n >> 2, b = n & 3;
    const int h = c >> 6, d = c & 63;
    float4 v = ((const float4*)vo)[i4];
    const size_t base = ((size_t)(b * H_DIM + h) * HD_DIM + d) * S_DIM + s;
    vT[base + 0 * S_DIM] = v.x;
    vT[base + 1 * S_DIM] = v.y;
    vT[base + 2 * S_DIM] = v.z;
    vT[base + 3 * S_DIM] = v.w;
}

// ctxh [bh, s, d] -> split bf16 at ctx row layout [(s*B+b)*D + h*64+d]
// 4 elems/thread, contiguous src and dst runs.
__global__ void reshape_ctx_split_kernel(const float* __restrict__ ctxh,
                                         __nv_bfloat16* __restrict__ hi,
                                         __nv_bfloat16* __restrict__ lo)
{
    const int i4 = blockIdx.x * 256 + threadIdx.x;    // over BH*S*HD/4
    const int idx = i4 * 4;
    const int bh  = idx >> 16;
    const int rem = idx & 65535;
    const int s = rem >> 6, d = rem & 63;
    const int b = bh >> 4, h = bh & 15;
    const size_t dst = ((size_t)(s * B_DIM + b) << 10) + h * HD_DIM + d;
    float4 v = ((const float4*)ctxh)[i4];
    __nv_bfloat16 h0 = __float2bfloat16(v.x);
    __nv_bfloat16 h1 = __float2bfloat16(v.y);
    __nv_bfloat16 h2 = __float2bfloat16(v.z);
    __nv_bfloat16 h3 = __float2bfloat16(v.w);
    __nv_bfloat162* hi2 = (__nv_bfloat162*)(hi + dst);
    __nv_bfloat162* lo2 = (__nv_bfloat162*)(lo + dst);
    hi2[0] = __nv_bfloat162(h0, h1);
    hi2[1] = __nv_bfloat162(h2, h3);
    lo2[0] = __nv_bfloat162(__float2bfloat16(v.x - __bfloat162float(h0)),
                            __float2bfloat16(v.y - __bfloat162float(h1)));
    lo2[1] = __nv_bfloat162(__float2bfloat16(v.z - __bfloat162float(h2)),
                            __float2bfloat16(v.w - __bfloat162float(h3)));
}

// ---------------------------------------------------------------------------
// Host side
// ---------------------------------------------------------------------------
template <typename T>
static T* sym_addr(const void* symbol)
{
    void* p = 0;
    cudaGetSymbolAddress(&p, symbol);
    return (T*)p;
}

extern "C" void kernel_launch(void* const* d_in, const int* in_sizes, int n_in,
                              void* d_out, int out_size)
{
    (void)n_in; (void)out_size; (void)in_sizes;

    const float* src       = (const float*)d_in[0];
    const float* pos       = (const float*)d_in[1];
    const float* in_proj_w = (const float*)d_in[2];
    const float* alpha_in  = (const float*)d_in[3];
    const float* out_proj_w= (const float*)d_in[4];
    const float* alpha_out = (const float*)d_in[5];
    const float* w1        = (const float*)d_in[6];
    const float* b1        = (const float*)d_in[7];
    const float* alpha1    = (const float*)d_in[8];
    const float* w2        = (const float*)d_in[9];
    const float* b2        = (const float*)d_in[10];
    const float* alpha2    = (const float*)d_in[11];
    const float* ln1_g     = (const float*)d_in[12];
    const float* ln1_b     = (const float*)d_in[13];
    const float* ln2_g     = (const float*)d_in[14];
    const float* ln2_b     = (const float*)d_in[15];
    float* out = (float*)d_out;

    __nv_bfloat16* p_wqin  = sym_addr<__nv_bfloat16>(g_wqin_b);
    __nv_bfloat16* p_wqout = sym_addr<__nv_bfloat16>(g_wqout_b);
    __nv_bfloat16* p_w1q   = sym_addr<__nv_bfloat16>(g_w1q_b);
    __nv_bfloat16* p_w2q   = sym_addr<__nv_bfloat16>(g_w2q_b);
    __nv_bfloat16* p_ah    = sym_addr<__nv_bfloat16>(g_ah);
    __nv_bfloat16* p_al    = sym_addr<__nv_bfloat16>(g_al);
    __nv_bfloat16* p_bh    = sym_addr<__nv_bfloat16>(g_bh);
    __nv_bfloat16* p_bl    = sym_addr<__nv_bfloat16>(g_bl);

    float* p_qko   = sym_addr<float>(g_qko);
    float* p_vo    = sym_addr<float>(g_vo);
    float* p_q     = sym_addr<float>(g_q);
    float* p_k     = sym_addr<float>(g_k);
    float* p_vT    = sym_addr<float>(g_vT);
    float* p_sc    = sym_addr<float>(g_scores);
    float* p_ctxh  = sym_addr<float>(g_ctxh);
    float* p_res1  = sym_addr<float>(g_res1);

    const int n_in_proj = 3 * D_DIM * D_DIM;
    const int n_out     = D_DIM * D_DIM;
    const int n_w1      = DFF_DIM * D_DIM;
    const int n_w2      = D_DIM * DFF_DIM;
    const float gi = (float)(1.0 / sqrt((double)n_in_proj * 7.0));
    const float go = (float)(1.0 / sqrt((double)n_out * 7.0));
    const float g1 = (float)(1.0 / sqrt((double)n_w1 * 7.0));
    const float g2 = (float)(1.0 / sqrt((double)n_w2 * 7.0));

    // ---- 1. quantize weights to integer bf16 (vec4) ---------------------
    quantq_kernel<<<(n_in_proj / 4 + 255) / 256, 256>>>(in_proj_w, p_wqin, n_in_proj / 4, alpha_in, gi);
    quantq_kernel<<<(n_out     / 4 + 255) / 256, 256>>>(out_proj_w, p_wqout, n_out / 4, alpha_out, go);
    quantq_kernel<<<(n_w1      / 4 + 255) / 256, 256>>>(w1, p_w1q, n_w1 / 4, alpha1, g1);
    quantq_kernel<<<(n_w2      / 4 + 255) / 256, 256>>>(w2, p_w2q, n_w2 / 4, alpha2, g2);

    // ---- 2. LN1 -> splits: pairB = split(src2), pairA = split(src2+pos) --
    ln_split_kernel<<<NTOK, 256>>>(src, ln1_g, ln1_b, pos,
                                   p_bh, p_bl,      // src2 split
                                   p_ah, p_al);     // qk split

    // ---- 3a. q|k projection: (qk) @ Wqk^T -> qko -------------------------
    gemm_bf16<<<dim3(2048 / 128, NTOK / 128), 256>>>(
        p_ah, p_al, p_wqin, p_qko, 0, 0, NTOK, 2048, D_DIM, alpha_in, gi, 0, 0, 0);

    // ---- 3b. v projection: (src2) @ Wv^T -> vo ---------------------------
    gemm_bf16<<<dim3(1024 / 128, NTOK / 128), 256>>>(
        p_bh, p_bl, p_wqin + (size_t)2048 * D_DIM, p_vo, 0, 0, NTOK, 1024, D_DIM,
        alpha_in, gi, 0, 0, 0);

    // ---- 4. reshapes (vec4) ----------------------------------------------
    split_qk_kernel <<<(NTOK * 2048 / 4) / 256, 256>>>(p_qko, p_q, p_k);
    reshape_v_kernel<<<(NTOK * 1024 / 4) / 256, 256>>>(p_vo, p_vT);

    // ---- 5. scores = q @ k^T  (batched over 64 heads) --------------------
    gemm_abt<<<dim3(S_DIM / GBN, S_DIM / GBM, BH), 256>>>(
        p_q, p_k, p_sc, S_DIM, S_DIM, HD_DIM,
        (size_t)S_DIM * HD_DIM, (size_t)S_DIM * HD_DIM, (size_t)S_DIM * S_DIM);

    // ---- 6. softmax ------------------------------------------------------
    softmax_kernel<<<BH * S_DIM, 256>>>(p_sc);

    // ---- 7. ctx = attn @ v -----------------------------------------------
    gemm_abt<<<dim3(HD_DIM / GBN, S_DIM / GBM, BH), 256>>>(
        p_sc, p_vT, p_ctxh, S_DIM, HD_DIM, S_DIM,
        (size_t)S_DIM * S_DIM, (size_t)HD_DIM * S_DIM, (size_t)S_DIM * HD_DIM);

    // ---- 8. ctx reshape + split -> pairA (vec4) --------------------------
    reshape_ctx_split_kernel<<<(BH * S_DIM * HD_DIM / 4) / 256, 256>>>(p_ctxh, p_ah, p_al);

    // ---- 9. out_proj + residual(src) -> res1 (fp32) ----------------------
    gemm_bf16<<<dim3(1024 / 128, NTOK / 128), 256>>>(
        p_ah, p_al, p_wqout, p_res1, 0, 0, NTOK, D_DIM, D_DIM, alpha_out, go, 0, src, 0);

    // ---- 10. LN2 -> pairB = split(src2b) ---------------------------------
    ln_split_kernel<<<NTOK, 256>>>(p_res1, ln2_g, ln2_b, 0,
                                   p_bh, p_bl, 0, 0);

    // ---- 11. FFN1: relu(src2b @ w1^T + b1) -> split into pairA -----------
    gemm_bf16<<<dim3(DFF_DIM / 128, NTOK / 128), 256>>>(
        p_bh, p_bl, p_w1q, 0, p_ah, p_al, NTOK, DFF_DIM, D_DIM, alpha1, g1, b1, 0, 1);

    // ---- 12. FFN2: res1 + h @ w2^T + b2  -> output (fp32) ----------------
    gemm_bf16<<<dim3(1024 / 128, NTOK / 128), 256>>>(
        p_ah, p_al, p_w2q, out, 0, 0, NTOK, D_DIM, DFF_DIM, alpha2, g2, b2, p_res1, 0);
}

// round 10
// speedup vs baseline: 1.9138x; 1.1540x over previous
#include <cuda_runtime.h>
#include <cuda_bf16.h>
#include <mma.h>
#include <math.h>
#include <stdint.h>

using namespace nvcuda;

// ---------------------------------------------------------------------------
// Problem constants
// ---------------------------------------------------------------------------
#define S_DIM   1024
#define B_DIM   4
#define D_DIM   1024
#define H_DIM   16
#define HD_DIM  64
#define DFF_DIM 4096
#define NTOK    4096          // S*B
#define BH      64            // B*H

// ---------------------------------------------------------------------------
// Device scratch
// ---------------------------------------------------------------------------
__device__ __nv_bfloat16 g_wqin_b [3 * D_DIM * D_DIM];
__device__ __nv_bfloat16 g_wqout_b[D_DIM * D_DIM];
__device__ __nv_bfloat16 g_w1q_b  [DFF_DIM * D_DIM];
__device__ __nv_bfloat16 g_w2q_b  [D_DIM * DFF_DIM];

// activation split pairs (GEMM A operands)
__device__ __nv_bfloat16 g_ah[NTOK * DFF_DIM];
__device__ __nv_bfloat16 g_al[NTOK * DFF_DIM];
__device__ __nv_bfloat16 g_bh[NTOK * D_DIM];
__device__ __nv_bfloat16 g_bl[NTOK * D_DIM];

// attention operands, bf16 hi/lo
__device__ __nv_bfloat16 g_qh[BH * S_DIM * HD_DIM];  // [b,h,s,d] (scaled 0.125)
__device__ __nv_bfloat16 g_ql[BH * S_DIM * HD_DIM];
__device__ __nv_bfloat16 g_kh[BH * S_DIM * HD_DIM];
__device__ __nv_bfloat16 g_kl[BH * S_DIM * HD_DIM];
__device__ __nv_bfloat16 g_vth[BH * HD_DIM * S_DIM]; // [b,h,d,s]
__device__ __nv_bfloat16 g_vtl[BH * HD_DIM * S_DIM];
__device__ __nv_bfloat16 g_anh[(size_t)BH * S_DIM * S_DIM];  // attn hi (128 MB)
__device__ __nv_bfloat16 g_anl[(size_t)BH * S_DIM * S_DIM];  // attn lo

__device__ float g_qko  [NTOK * 2 * D_DIM];      // q|k projection output
__device__ float g_vo   [NTOK * D_DIM];          // v projection output
__device__ float g_scores[(size_t)BH * S_DIM * S_DIM];   // 256 MB fp32
__device__ float g_ctxh [BH * S_DIM * HD_DIM];   // [b,h,s,d]
__device__ float g_res1 [NTOK * D_DIM];

// ---------------------------------------------------------------------------
// LSQ quantization to INTEGER bf16 (vec4)
// ---------------------------------------------------------------------------
__global__ void quantq_kernel(const float* __restrict__ w, __nv_bfloat16* __restrict__ o,
                              int n4, const float* __restrict__ alpha_p, float g)
{
    int i = blockIdx.x * blockDim.x + threadIdx.x;
    if (i >= n4) return;
    float alpha = *alpha_p;
    float ag = alpha * g;
    float a  = ag + (alpha - ag);
    float inv_a = 1.0f / a;
    float4 v = ((const float4*)w)[i];
    float q0 = rintf(fminf(fmaxf(v.x * inv_a, -8.0f), 7.0f));
    float q1 = rintf(fminf(fmaxf(v.y * inv_a, -8.0f), 7.0f));
    float q2 = rintf(fminf(fmaxf(v.z * inv_a, -8.0f), 7.0f));
    float q3 = rintf(fminf(fmaxf(v.w * inv_a, -8.0f), 7.0f));
    __nv_bfloat162* o2 = (__nv_bfloat162*)o;
    o2[i * 2 + 0] = __nv_bfloat162(__float2bfloat16(q0), __float2bfloat16(q1));
    o2[i * 2 + 1] = __nv_bfloat162(__float2bfloat16(q2), __float2bfloat16(q3));
}

// ---------------------------------------------------------------------------
// LayerNorm with fused bf16 hi/lo splits
// ---------------------------------------------------------------------------
__global__ void ln_split_kernel(const float* __restrict__ x,
                                const float* __restrict__ gamma,
                                const float* __restrict__ beta,
                                const float* __restrict__ pos,
                                __nv_bfloat16* __restrict__ out_hi,
                                __nv_bfloat16* __restrict__ out_lo,
                                __nv_bfloat16* __restrict__ qk_hi,
                                __nv_bfloat16* __restrict__ qk_lo)
{
    const int n = blockIdx.x;
    const float* row = x + (size_t)n * D_DIM;
    __shared__ float sh[D_DIM];
    __shared__ float red[256];
    const int tid = threadIdx.x;

    float s = 0.0f;
    #pragma unroll
    for (int i = tid; i < D_DIM; i += 256) { float v = row[i]; sh[i] = v; s += v; }
    red[tid] = s;
    __syncthreads();
    for (int st = 128; st > 0; st >>= 1) {
        if (tid < st) red[tid] += red[tid + st];
        __syncthreads();
    }
    const float mean = red[0] * (1.0f / D_DIM);
    __syncthreads();

    float vs = 0.0f;
    #pragma unroll
    for (int i = tid; i < D_DIM; i += 256) { float d = sh[i] - mean; vs += d * d; }
    red[tid] = vs;
    __syncthreads();
    for (int st = 128; st > 0; st >>= 1) {
        if (tid < st) red[tid] += red[tid + st];
        __syncthreads();
    }
    const float var = red[0] * (1.0f / D_DIM);
    const float inv = rsqrtf(var + 1e-5f);

    #pragma unroll
    for (int i = tid; i < D_DIM; i += 256) {
        const size_t off = (size_t)n * D_DIM + i;
        float y = (sh[i] - mean) * inv * gamma[i] + beta[i];
        if (out_hi) {
            __nv_bfloat16 h = __float2bfloat16(y);
            out_hi[off] = h;
            out_lo[off] = __float2bfloat16(y - __bfloat162float(h));
        }
        if (qk_hi) {
            float z = y + pos[off];
            __nv_bfloat16 h = __float2bfloat16(z);
            qk_hi[off] = h;
            qk_lo[off] = __float2bfloat16(z - __bfloat162float(h));
        }
    }
}

// ---------------------------------------------------------------------------
// Weight GEMM: acc = (Ah+Al)[M,K] @ Q[N,K]^T ; epilogue scale/bias/res/relu,
// optional bf16 split output. 128x128 tile, K-tile 32, 8 warps.
// ---------------------------------------------------------------------------
#define WTS 40

__global__ void __launch_bounds__(256, 1)
gemm_bf16(const __nv_bfloat16* __restrict__ Ah,
          const __nv_bfloat16* __restrict__ Al,
          const __nv_bfloat16* __restrict__ Bq,
          float* __restrict__ C,
          __nv_bfloat16* __restrict__ Chi,
          __nv_bfloat16* __restrict__ Clo,
          int M, int N, int K,
          const float* __restrict__ alpha_p, float gscale,
          const float* __restrict__ bias,
          const float* __restrict__ res,
          int relu)
{
    __shared__ __nv_bfloat16 Ahs[128 * WTS];
    __shared__ __nv_bfloat16 Als[128 * WTS];
    __shared__ __nv_bfloat16 Bs [128 * WTS];
    __shared__ float scratch[8 * 256];

    const int tid = threadIdx.x;
    const int n0 = blockIdx.x * 128;
    const int m0 = blockIdx.y * 128;

    const int w  = tid >> 5;
    const int wm = w & 3;
    const int wn = w >> 2;

    wmma::fragment<wmma::accumulator, 16, 16, 16, float> acc[2][4];
    #pragma unroll
    for (int i = 0; i < 2; i++)
        #pragma unroll
        for (int j = 0; j < 4; j++)
            wmma::fill_fragment(acc[i][j], 0.0f);

    uint2 pa[4], pl[4], pb[4];

    #define LOAD_TILE_REGS(k0)                                                  \
        _Pragma("unroll")                                                       \
        for (int p = 0; p < 4; p++) {                                           \
            int lin = tid + p * 256;                                            \
            int r = lin >> 3;                                                   \
            int c = (lin & 7) * 4;                                              \
            pa[p] = *(const uint2*)(Ah + (size_t)(m0 + r) * K + (k0) + c);      \
            pl[p] = *(const uint2*)(Al + (size_t)(m0 + r) * K + (k0) + c);      \
            pb[p] = *(const uint2*)(Bq + (size_t)(n0 + r) * K + (k0) + c);      \
        }

    LOAD_TILE_REGS(0)

    for (int k0 = 0; k0 < K; k0 += 32) {
        #pragma unroll
        for (int p = 0; p < 4; p++) {
            int lin = tid + p * 256;
            int r = lin >> 3;
            int c = (lin & 7) * 4;
            *(uint2*)&Ahs[r * WTS + c] = pa[p];
            *(uint2*)&Als[r * WTS + c] = pl[p];
            *(uint2*)&Bs [r * WTS + c] = pb[p];
        }
        __syncthreads();

        if (k0 + 32 < K) { LOAD_TILE_REGS(k0 + 32) }

        #pragma unroll
        for (int kk = 0; kk < 32; kk += 16) {
            wmma::fragment<wmma::matrix_a, 16, 16, 16, __nv_bfloat16, wmma::row_major> fh[2], fl[2];
            wmma::fragment<wmma::matrix_b, 16, 16, 16, __nv_bfloat16, wmma::col_major> fb[4];
            #pragma unroll
            for (int i = 0; i < 2; i++) {
                wmma::load_matrix_sync(fh[i], &Ahs[(wm * 32 + i * 16) * WTS + kk], WTS);
                wmma::load_matrix_sync(fl[i], &Als[(wm * 32 + i * 16) * WTS + kk], WTS);
            }
            #pragma unroll
            for (int j = 0; j < 4; j++)
                wmma::load_matrix_sync(fb[j], &Bs[(wn * 64 + j * 16) * WTS + kk], WTS);

            #pragma unroll
            for (int i = 0; i < 2; i++)
                #pragma unroll
                for (int j = 0; j < 4; j++) {
                    wmma::mma_sync(acc[i][j], fh[i], fb[j], acc[i][j]);
                    wmma::mma_sync(acc[i][j], fl[i], fb[j], acc[i][j]);
                }
        }
        __syncthreads();
    }

    const float alpha = *alpha_p;
    const float ag = alpha * gscale;
    const float a  = ag + (alpha - ag);

    float* sw = &scratch[w * 256];
    const int lane = tid & 31;

    #pragma unroll
    for (int i = 0; i < 2; i++) {
        #pragma unroll
        for (int j = 0; j < 4; j++) {
            wmma::store_matrix_sync(sw, acc[i][j], 16, wmma::mem_row_major);
            __syncwarp();
            #pragma unroll
            for (int t = 0; t < 8; t++) {
                int idx = lane + t * 32;
                int r = idx >> 4, c = idx & 15;
                int m = m0 + wm * 32 + i * 16 + r;
                int n = n0 + wn * 64 + j * 16 + c;
                float v = sw[idx] * a;
                if (bias) v += bias[n];
                if (res)  v += res[(size_t)m * N + n];
                if (relu) v = fmaxf(v, 0.0f);
                const size_t off = (size_t)m * N + n;
                if (Chi) {
                    __nv_bfloat16 h = __float2bfloat16(v);
                    Chi[off] = h;
                    Clo[off] = __float2bfloat16(v - __bfloat162float(h));
                } else {
                    C[off] = v;
                }
            }
            __syncwarp();
        }
    }
}

// ---------------------------------------------------------------------------
// Batched attention GEMM on tensor cores, both operands hi/lo split:
//   C[M,N] = (Ah+Al)[M,K] @ ((Bh+Bl)[N,K])^T     (3-stream mma, AlBl dropped)
// Block tile 128 x BN (BN = 128 or 64), K-tile 32, 8 warps (4 M x 2 N).
// ---------------------------------------------------------------------------
template <int BN>
__global__ void __launch_bounds__(256, 1)
gemm_attn(const __nv_bfloat16* __restrict__ Ah_, const __nv_bfloat16* __restrict__ Al_,
          const __nv_bfloat16* __restrict__ Bh_, const __nv_bfloat16* __restrict__ Bl_,
          float* __restrict__ C_, int M, int N, int K,
          size_t sA, size_t sB, size_t sC)
{
    constexpr int NF = BN / 32;        // 16-col frags per warp (wn covers BN/2)
    constexpr int PB = BN / 32;        // uint2 loads per thread for B tiles

    const __nv_bfloat16* Ah = Ah_ + (size_t)blockIdx.z * sA;
    const __nv_bfloat16* Al = Al_ + (size_t)blockIdx.z * sA;
    const __nv_bfloat16* Bh = Bh_ + (size_t)blockIdx.z * sB;
    const __nv_bfloat16* Bl = Bl_ + (size_t)blockIdx.z * sB;
    float*               C  = C_  + (size_t)blockIdx.z * sC;

    __shared__ __nv_bfloat16 Ahs[128 * WTS];
    __shared__ __nv_bfloat16 Als[128 * WTS];
    __shared__ __nv_bfloat16 Bhs[BN * WTS];
    __shared__ __nv_bfloat16 Bls[BN * WTS];
    __shared__ float scratch[8 * 256];

    const int tid = threadIdx.x;
    const int n0 = blockIdx.x * BN;
    const int m0 = blockIdx.y * 128;

    const int w  = tid >> 5;
    const int wm = w & 3;
    const int wn = w >> 2;

    wmma::fragment<wmma::accumulator, 16, 16, 16, float> acc[2][NF];
    #pragma unroll
    for (int i = 0; i < 2; i++)
        #pragma unroll
        for (int j = 0; j < NF; j++)
            wmma::fill_fragment(acc[i][j], 0.0f);

    uint2 pah[4], pal[4], pbh[PB], pbl[PB];

    #define LOAD_ATTN_REGS(k0)                                                  \
        _Pragma("unroll")                                                       \
        for (int p = 0; p < 4; p++) {                                           \
            int lin = tid + p * 256;                                            \
            int r = lin >> 3;                                                   \
            int c = (lin & 7) * 4;                                              \
            pah[p] = *(const uint2*)(Ah + (size_t)(m0 + r) * K + (k0) + c);     \
            pal[p] = *(const uint2*)(Al + (size_t)(m0 + r) * K + (k0) + c);     \
        }                                                                       \
        _Pragma("unroll")                                                       \
        for (int p = 0; p < PB; p++) {                                          \
            int lin = tid + p * 256;                                            \
            int r = lin >> 3;                                                   \
            int c = (lin & 7) * 4;                                              \
            pbh[p] = *(const uint2*)(Bh + (size_t)(n0 + r) * K + (k0) + c);     \
            pbl[p] = *(const uint2*)(Bl + (size_t)(n0 + r) * K + (k0) + c);     \
        }

    LOAD_ATTN_REGS(0)

    for (int k0 = 0; k0 < K; k0 += 32) {
        #pragma unroll
        for (int p = 0; p < 4; p++) {
            int lin = tid + p * 256;
            int r = lin >> 3;
            int c = (lin & 7) * 4;
            *(uint2*)&Ahs[r * WTS + c] = pah[p];
            *(uint2*)&Als[r * WTS + c] = pal[p];
        }
        #pragma unroll
        for (int p = 0; p < PB; p++) {
            int lin = tid + p * 256;
            int r = lin >> 3;
            int c = (lin & 7) * 4;
            *(uint2*)&Bhs[r * WTS + c] = pbh[p];
            *(uint2*)&Bls[r * WTS + c] = pbl[p];
        }
        __syncthreads();

        if (k0 + 32 < K) { LOAD_ATTN_REGS(k0 + 32) }

        #pragma unroll
        for (int kk = 0; kk < 32; kk += 16) {
            wmma::fragment<wmma::matrix_a, 16, 16, 16, __nv_bfloat16, wmma::row_major> fah[2], fal[2];
            wmma::fragment<wmma::matrix_b, 16, 16, 16, __nv_bfloat16, wmma::col_major> fbh[NF], fbl[NF];
            #pragma unroll
            for (int i = 0; i < 2; i++) {
                wmma::load_matrix_sync(fah[i], &Ahs[(wm * 32 + i * 16) * WTS + kk], WTS);
                wmma::load_matrix_sync(fal[i], &Als[(wm * 32 + i * 16) * WTS + kk], WTS);
            }
            #pragma unroll
            for (int j = 0; j < NF; j++) {
                wmma::load_matrix_sync(fbh[j], &Bhs[(wn * (BN / 2) + j * 16) * WTS + kk], WTS);
                wmma::load_matrix_sync(fbl[j], &Bls[(wn * (BN / 2) + j * 16) * WTS + kk], WTS);
            }
            #pragma unroll
            for (int i = 0; i < 2; i++)
                #pragma unroll
                for (int j = 0; j < NF; j++) {
                    wmma::mma_sync(acc[i][j], fah[i], fbh[j], acc[i][j]);
                    wmma::mma_sync(acc[i][j], fah[i], fbl[j], acc[i][j]);
                    wmma::mma_sync(acc[i][j], fal[i], fbh[j], acc[i][j]);
                }
        }
        __syncthreads();
    }

    float* sw = &scratch[w * 256];
    const int lane = tid & 31;

    #pragma unroll
    for (int i = 0; i < 2; i++) {
        #pragma unroll
        for (int j = 0; j < NF; j++) {
            wmma::store_matrix_sync(sw, acc[i][j], 16, wmma::mem_row_major);
            __syncwarp();
            #pragma unroll
            for (int t = 0; t < 8; t++) {
                int idx = lane + t * 32;
                int r = idx >> 4, c = idx & 15;
                int m = m0 + wm * 32 + i * 16 + r;
                int n = n0 + wn * (BN / 2) + j * 16 + c;
                C[(size_t)m * N + n] = sw[idx];
            }
            __syncwarp();
        }
    }
}

// ---------------------------------------------------------------------------
// Row softmax (1024), register-resident, writes bf16 hi/lo. 256 threads,
// 4 elems/thread via float4.
// ---------------------------------------------------------------------------
__global__ void softmax_split_kernel(const float* __restrict__ p,
                                     __nv_bfloat16* __restrict__ hi,
                                     __nv_bfloat16* __restrict__ lo)
{
    const size_t row = (size_t)blockIdx.x * S_DIM;
    const int tid = threadIdx.x;
    __shared__ float red[256];

    float4 v = ((const float4*)(p + row))[tid];

    float m = fmaxf(fmaxf(v.x, v.y), fmaxf(v.z, v.w));
    red[tid] = m;
    __syncthreads();
    for (int st = 128; st > 0; st >>= 1) {
        if (tid < st) red[tid] = fmaxf(red[tid], red[tid + st]);
        __syncthreads();
    }
    m = red[0];
    __syncthreads();

    float e0 = expf(v.x - m), e1 = expf(v.y - m), e2 = expf(v.z - m), e3 = expf(v.w - m);
    red[tid] = e0 + e1 + e2 + e3;
    __syncthreads();
    for (int st = 128; st > 0; st >>= 1) {
        if (tid < st) red[tid] += red[tid + st];
        __syncthreads();
    }
    const float inv = 1.0f / red[0];

    e0 *= inv; e1 *= inv; e2 *= inv; e3 *= inv;
    __nv_bfloat16 h0 = __float2bfloat16(e0);
    __nv_bfloat16 h1 = __float2bfloat16(e1);
    __nv_bfloat16 h2 = __float2bfloat16(e2);
    __nv_bfloat16 h3 = __float2bfloat16(e3);
    __nv_bfloat162* hi2 = (__nv_bfloat162*)(hi + row) + tid * 2;
    __nv_bfloat162* lo2 = (__nv_bfloat162*)(lo + row) + tid * 2;
    hi2[0] = __nv_bfloat162(h0, h1);
    hi2[1] = __nv_bfloat162(h2, h3);
    lo2[0] = __nv_bfloat162(__float2bfloat16(e0 - __bfloat162float(h0)),
                            __float2bfloat16(e1 - __bfloat162float(h1)));
    lo2[1] = __nv_bfloat162(__float2bfloat16(e2 - __bfloat162float(h2)),
                            __float2bfloat16(e3 - __bfloat162float(h3)));
}

// ---------------------------------------------------------------------------
// Reshape kernels
// ---------------------------------------------------------------------------
// qko [N,2048] -> qh/ql (scaled 0.125), kh/kl at [b,h,s,d]; 4 elems/thread.
__global__ void split_qk_kernel(const float* __restrict__ qko,
                                __nv_bfloat16* __restrict__ qh, __nv_bfloat16* __restrict__ ql,
                                __nv_bfloat16* __restrict__ kh, __nv_bfloat16* __restrict__ kl)
{
    const int i4 = blockIdx.x * 256 + threadIdx.x;
    const int idx = i4 * 4;
    const int n = idx >> 11;
    const int c = idx & 2047;
    const int s = n >> 2, b = n & 3;
    float4 v = ((const float4*)qko)[i4];
    __nv_bfloat16* dh; __nv_bfloat16* dl;
    size_t dst;
    if (c < 1024) {
        const int h = c >> 6, d = c & 63;
        dst = (((size_t)(b * H_DIM + h) * S_DIM + s) << 6) + d;
        v.x *= 0.125f; v.y *= 0.125f; v.z *= 0.125f; v.w *= 0.125f;
        dh = qh; dl = ql;
    } else {
        const int c2 = c - 1024;
        const int h = c2 >> 6, d = c2 & 63;
        dst = (((size_t)(b * H_DIM + h) * S_DIM + s) << 6) + d;
        dh = kh; dl = kl;
    }
    __nv_bfloat16 h0 = __float2bfloat16(v.x);
    __nv_bfloat16 h1 = __float2bfloat16(v.y);
    __nv_bfloat16 h2 = __float2bfloat16(v.z);
    __nv_bfloat16 h3 = __float2bfloat16(v.w);
    __nv_bfloat162* dh2 = (__nv_bfloat162*)(dh + dst);
    __nv_bfloat162* dl2 = (__nv_bfloat162*)(dl + dst);
    dh2[0] = __nv_bfloat162(h0, h1);
    dh2[1] = __nv_bfloat162(h2, h3);
    dl2[0] = __nv_bfloat162(__float2bfloat16(v.x - __bfloat162float(h0)),
                            __float2bfloat16(v.y - __bfloat162float(h1)));
    dl2[1] = __nv_bfloat162(__float2bfloat16(v.z - __bfloat162float(h2)),
                            __float2bfloat16(v.w - __bfloat162float(h3)));
}

// vo [N,1024] -> vT hi/lo [b,h,d,s]  (vec4 read, scattered scalar writes)
__global__ void reshape_v_kernel(const float* __restrict__ vo,
                                 __nv_bfloat16* __restrict__ vth,
                                 __nv_bfloat16* __restrict__ vtl)
{
    const int i4 = blockIdx.x * 256 + threadIdx.x;
    const int idx = i4 * 4;
    const int n = idx >> 10;
    const int c = idx & 1023;
    const int s = n >> 2, b = n & 3;
    const int h = c >> 6, d = c & 63;
    float4 v = ((const float4*)vo)[i4];
    const size_t base = ((size_t)(b * H_DIM + h) * HD_DIM + d) * S_DIM + s;
    float vv[4] = {v.x, v.y, v.z, v.w};
    #pragma unroll
    for (int t = 0; t < 4; t++) {
        __nv_bfloat16 hh = __float2bfloat16(vv[t]);
        vth[base + t * S_DIM] = hh;
        vtl[base + t * S_DIM] = __float2bfloat16(vv[t] - __bfloat162float(hh));
    }
}

// ctxh [bh,s,d] -> split bf16 at ctx row layout [(s*B+b)*D + h*64+d]
__global__ void reshape_ctx_split_kernel(const float* __restrict__ ctxh,
                                         __nv_bfloat16* __restrict__ hi,
                                         __nv_bfloat16* __restrict__ lo)
{
    const int i4 = blockIdx.x * 256 + threadIdx.x;
    const int idx = i4 * 4;
    const int bh  = idx >> 16;
    const int rem = idx & 65535;
    const int s = rem >> 6, d = rem & 63;
    const int b = bh >> 4, h = bh & 15;
    const size_t dst = ((size_t)(s * B_DIM + b) << 10) + h * HD_DIM + d;
    float4 v = ((const float4*)ctxh)[i4];
    __nv_bfloat16 h0 = __float2bfloat16(v.x);
    __nv_bfloat16 h1 = __float2bfloat16(v.y);
    __nv_bfloat16 h2 = __float2bfloat16(v.z);
    __nv_bfloat16 h3 = __float2bfloat16(v.w);
    __nv_bfloat162* hi2 = (__nv_bfloat162*)(hi + dst);
    __nv_bfloat162* lo2 = (__nv_bfloat162*)(lo + dst);
    hi2[0] = __nv_bfloat162(h0, h1);
    hi2[1] = __nv_bfloat162(h2, h3);
    lo2[0] = __nv_bfloat162(__float2bfloat16(v.x - __bfloat162float(h0)),
                            __float2bfloat16(v.y - __bfloat162float(h1)));
    lo2[1] = __nv_bfloat162(__float2bfloat16(v.z - __bfloat162float(h2)),
                            __float2bfloat16(v.w - __bfloat162float(h3)));
}

// ---------------------------------------------------------------------------
// Host side
// ---------------------------------------------------------------------------
template <typename T>
static T* sym_addr(const void* symbol)
{
    void* p = 0;
    cudaGetSymbolAddress(&p, symbol);
    return (T*)p;
}

extern "C" void kernel_launch(void* const* d_in, const int* in_sizes, int n_in,
                              void* d_out, int out_size)
{
    (void)n_in; (void)out_size; (void)in_sizes;

    const float* src       = (const float*)d_in[0];
    const float* pos       = (const float*)d_in[1];
    const float* in_proj_w = (const float*)d_in[2];
    const float* alpha_in  = (const float*)d_in[3];
    const float* out_proj_w= (const float*)d_in[4];
    const float* alpha_out = (const float*)d_in[5];
    const float* w1        = (const float*)d_in[6];
    const float* b1        = (const float*)d_in[7];
    const float* alpha1    = (const float*)d_in[8];
    const float* w2        = (const float*)d_in[9];
    const float* b2        = (const float*)d_in[10];
    const float* alpha2    = (const float*)d_in[11];
    const float* ln1_g     = (const float*)d_in[12];
    const float* ln1_b     = (const float*)d_in[13];
    const float* ln2_g     = (const float*)d_in[14];
    const float* ln2_b     = (const float*)d_in[15];
    float* out = (float*)d_out;

    __nv_bfloat16* p_wqin  = sym_addr<__nv_bfloat16>(g_wqin_b);
    __nv_bfloat16* p_wqout = sym_addr<__nv_bfloat16>(g_wqout_b);
    __nv_bfloat16* p_w1q   = sym_addr<__nv_bfloat16>(g_w1q_b);
    __nv_bfloat16* p_w2q   = sym_addr<__nv_bfloat16>(g_w2q_b);
    __nv_bfloat16* p_ah    = sym_addr<__nv_bfloat16>(g_ah);
    __nv_bfloat16* p_al    = sym_addr<__nv_bfloat16>(g_al);
    __nv_bfloat16* p_bh    = sym_addr<__nv_bfloat16>(g_bh);
    __nv_bfloat16* p_bl    = sym_addr<__nv_bfloat16>(g_bl);
    __nv_bfloat16* p_qh    = sym_addr<__nv_bfloat16>(g_qh);
    __nv_bfloat16* p_ql    = sym_addr<__nv_bfloat16>(g_ql);
    __nv_bfloat16* p_kh    = sym_addr<__nv_bfloat16>(g_kh);
    __nv_bfloat16* p_kl    = sym_addr<__nv_bfloat16>(g_kl);
    __nv_bfloat16* p_vth   = sym_addr<__nv_bfloat16>(g_vth);
    __nv_bfloat16* p_vtl   = sym_addr<__nv_bfloat16>(g_vtl);
    __nv_bfloat16* p_anh   = sym_addr<__nv_bfloat16>(g_anh);
    __nv_bfloat16* p_anl   = sym_addr<__nv_bfloat16>(g_anl);

    float* p_qko   = sym_addr<float>(g_qko);
    float* p_vo    = sym_addr<float>(g_vo);
    float* p_sc    = sym_addr<float>(g_scores);
    float* p_ctxh  = sym_addr<float>(g_ctxh);
    float* p_res1  = sym_addr<float>(g_res1);

    const int n_in_proj = 3 * D_DIM * D_DIM;
    const int n_out     = D_DIM * D_DIM;
    const int n_w1      = DFF_DIM * D_DIM;
    const int n_w2      = D_DIM * DFF_DIM;
    const float gi = (float)(1.0 / sqrt((double)n_in_proj * 7.0));
    const float go = (float)(1.0 / sqrt((double)n_out * 7.0));
    const float g1 = (float)(1.0 / sqrt((double)n_w1 * 7.0));
    const float g2 = (float)(1.0 / sqrt((double)n_w2 * 7.0));

    // ---- 1. quantize weights --------------------------------------------
    quantq_kernel<<<(n_in_proj / 4 + 255) / 256, 256>>>(in_proj_w, p_wqin, n_in_proj / 4, alpha_in, gi);
    quantq_kernel<<<(n_out     / 4 + 255) / 256, 256>>>(out_proj_w, p_wqout, n_out / 4, alpha_out, go);
    quantq_kernel<<<(n_w1      / 4 + 255) / 256, 256>>>(w1, p_w1q, n_w1 / 4, alpha1, g1);
    quantq_kernel<<<(n_w2      / 4 + 255) / 256, 256>>>(w2, p_w2q, n_w2 / 4, alpha2, g2);

    // ---- 2. LN1 -> pairB = split(src2), pairA = split(src2+pos) ----------
    ln_split_kernel<<<NTOK, 256>>>(src, ln1_g, ln1_b, pos,
                                   p_bh, p_bl, p_ah, p_al);

    // ---- 3. projections ---------------------------------------------------
    gemm_bf16<<<dim3(2048 / 128, NTOK / 128), 256>>>(
        p_ah, p_al, p_wqin, p_qko, 0, 0, NTOK, 2048, D_DIM, alpha_in, gi, 0, 0, 0);
    gemm_bf16<<<dim3(1024 / 128, NTOK / 128), 256>>>(
        p_bh, p_bl, p_wqin + (size_t)2048 * D_DIM, p_vo, 0, 0, NTOK, 1024, D_DIM,
        alpha_in, gi, 0, 0, 0);

    // ---- 4. reshapes -> bf16 hi/lo attention operands ---------------------
    split_qk_kernel <<<(NTOK * 2048 / 4) / 256, 256>>>(p_qko, p_qh, p_ql, p_kh, p_kl);
    reshape_v_kernel<<<(NTOK * 1024 / 4) / 256, 256>>>(p_vo, p_vth, p_vtl);

    // ---- 5. scores = q @ k^T (tensor cores, batched 64) -------------------
    gemm_attn<128><<<dim3(S_DIM / 128, S_DIM / 128, BH), 256>>>(
        p_qh, p_ql, p_kh, p_kl, p_sc, S_DIM, S_DIM, HD_DIM,
        (size_t)S_DIM * HD_DIM, (size_t)S_DIM * HD_DIM, (size_t)S_DIM * S_DIM);

    // ---- 6. softmax -> attn hi/lo bf16 ------------------------------------
    softmax_split_kernel<<<BH * S_DIM, 256>>>(p_sc, p_anh, p_anl);

    // ---- 7. ctx = attn @ v (tensor cores, batched 64) ---------------------
    gemm_attn<64><<<dim3(HD_DIM / 64, S_DIM / 128, BH), 256>>>(
        p_anh, p_anl, p_vth, p_vtl, p_ctxh, S_DIM, HD_DIM, S_DIM,
        (size_t)S_DIM * S_DIM, (size_t)HD_DIM * S_DIM, (size_t)S_DIM * HD_DIM);

    // ---- 8. ctx reshape + split -> pairA ----------------------------------
    reshape_ctx_split_kernel<<<(BH * S_DIM * HD_DIM / 4) / 256, 256>>>(p_ctxh, p_ah, p_al);

    // ---- 9. out_proj + residual(src) -> res1 ------------------------------
    gemm_bf16<<<dim3(1024 / 128, NTOK / 128), 256>>>(
        p_ah, p_al, p_wqout, p_res1, 0, 0, NTOK, D_DIM, D_DIM, alpha_out, go, 0, src, 0);

    // ---- 10. LN2 -> pairB -------------------------------------------------
    ln_split_kernel<<<NTOK, 256>>>(p_res1, ln2_g, ln2_b, 0,
                                   p_bh, p_bl, 0, 0);

    // ---- 11. FFN1: relu(src2b @ w1^T + b1) -> pairA -----------------------
    gemm_bf16<<<dim3(DFF_DIM / 128, NTOK / 128), 256>>>(
        p_bh, p_bl, p_w1q, 0, p_ah, p_al, NTOK, DFF_DIM, D_DIM, alpha1, g1, b1, 0, 1);

    // ---- 12. FFN2: res1 + h @ w2^T + b2 -> output -------------------------
    gemm_bf16<<<dim3(1024 / 128, NTOK / 128), 256>>>(
        p_ah, p_al, p_w2q, out, 0, 0, NTOK, D_DIM, DFF_DIM, alpha2, g2, b2, p_res1, 0);
}